// round 10
// baseline (speedup 1.0000x reference)
#include <cuda_runtime.h>
#include <cstdint>
#include <math.h>

#define NB    8192
#define ND    1024
#define BM    128
#define BK    8
#define NT    64                      /* 8192/128 tiles per dim */
#define NPAIRS (NT*(NT+1)/2)          /* 2080 upper-triangle tiles */
#define SCALEF 28.85390081777927f     /* log2(e)/0.05 */

__device__ float g_sum[NB];   // sum_j exp(sim_ij)
__device__ float g_num[NB];   // sum over positives
__device__ int   g_is64;      // relations dtype flag (1 if serialized int64)
__device__ int   g_truw;      // is_true mode: 1 = 4-byte words (f32/i32), 0 = bytes

// ---------------------------------------------------------------- init/probe
__global__ void init_kernel() {
    int i = blockIdx.x * blockDim.x + threadIdx.x;
    if (i < NB) { g_sum[i] = 0.f; g_num[i] = 0.f; }
}

// Dtype probes (all reads in-bounds for every candidate encoding):
// relations: if int64 (LE), int32 view has zero high words at odd indices
//            (values in [0,128)); if int32, odd entries are random nonzero.
// is_true:   classify from first 2048 words:
//            any word == 0x3F800000 -> float32 (truth = word != 0)
//            else any word > 1      -> bytes   (bool/uint8: bytes in {0,1})
//            else                   -> int32   (truth = word != 0)
__global__ void probe_kernel(const int* __restrict__ rel32,
                             const unsigned int* __restrict__ truw) {
    __shared__ int rel_nz, f32_seen, gt1_seen;
    if (threadIdx.x == 0) { rel_nz = 0; f32_seen = 0; gt1_seen = 0; }
    __syncthreads();
    for (int i = 1 + 2 * threadIdx.x; i < NB; i += 2 * blockDim.x)
        if (rel32[i] != 0) rel_nz = 1;
    for (int i = threadIdx.x; i < NB / 4; i += blockDim.x) {
        unsigned int w = truw[i];
        if (w == 0x3F800000u) f32_seen = 1;
        else if (w > 1u) gt1_seen = 1;
    }
    __syncthreads();
    if (threadIdx.x == 0) {
        g_is64 = rel_nz ? 0 : 1;
        g_truw = (f32_seen || !gt1_seen) ? 1 : 0;
    }
}

// ---------------------------------------------------------------- main tiles
// One block = one 128x128 tile of sim, full K=1024, fused exp + masked sums.
// Upper triangle only; off-diagonal tiles feed both row- and col- accumulators
// (sim and the positive mask are symmetric).
// NOTE: no min-blocks clause — forcing 2 CTAs/SM (<=128 regs) risks spilling
// the 64-reg packed accumulator file; occ 1 is benign for an fma-bound loop.
__global__ __launch_bounds__(256)
void tile_kernel(const float* __restrict__ emb,
                 const int*   __restrict__ rel32,
                 const void*  __restrict__ tru) {
    __shared__ float smem[4096];          // double-buffered A/B tiles; reused for reduction
    __shared__ int rkey[BM], ckey[BM];

    // linear block id -> (bm, bn) with bn >= bm (runs once; <=64 iterations)
    int rem = blockIdx.x, bm = 0;
    while (rem >= NT - bm) { rem -= NT - bm; bm++; }
    const int bn = bm + rem;
    const int row0 = bm * BM, col0 = bn * BM;
    const bool diag = (bm == bn);

    const int tid = threadIdx.x;
    const int tx = tid & 15, ty = tid >> 4;

    {   // relation keys: key = is_true ? relation : -1 (never matches)
        const int is64 = g_is64;
        const int truw = g_truw;
        const unsigned int*  tw = (const unsigned int*)tru;
        const unsigned char* tb = (const unsigned char*)tru;
        if (tid < BM) {
            int r = row0 + tid;
            int rv = is64 ? rel32[2 * r] : rel32[r];
            bool t = truw ? (tw[r] != 0u) : (tb[r] != 0);
            rkey[tid] = t ? rv : -1;
        } else {
            int c = col0 + (tid - BM);
            int cv = is64 ? rel32[2 * c] : rel32[c];
            bool t = truw ? (tw[c] != 0u) : (tb[c] != 0);
            ckey[tid - BM] = t ? cv : -1;
        }
    }

#define AS(b,k,m)  smem[(b)*1024 + (k)*BM + (m)]
#define BS_(b,k,n) smem[2048 + (b)*1024 + (k)*BM + (n)]

    const int lrow = tid >> 1;            // 0..127
    const int lk4  = (tid & 1) * 4;       // 0 or 4
    const float4* aptr = (const float4*)(emb + (size_t)(row0 + lrow) * ND + lk4);
    const float4* bptr = (const float4*)(emb + (size_t)(col0 + lrow) * ND + lk4);

    float4 an  = aptr[0];
    float4 bn4 = bptr[0];

    // accumulators: 8 rows x 4 packed f32x2 column-pairs (full fp32 rate via FFMA2)
    unsigned long long acc2[8][4];
#pragma unroll
    for (int i = 0; i < 8; i++)
#pragma unroll
        for (int j = 0; j < 4; j++) acc2[i][j] = 0ull;

    int buf = 0;
#pragma unroll 1
    for (int kt = 0; kt < ND / BK; kt++) {
        AS(buf, lk4 + 0, lrow) = an.x;
        AS(buf, lk4 + 1, lrow) = an.y;
        AS(buf, lk4 + 2, lrow) = an.z;
        AS(buf, lk4 + 3, lrow) = an.w;
        BS_(buf, lk4 + 0, lrow) = bn4.x;
        BS_(buf, lk4 + 1, lrow) = bn4.y;
        BS_(buf, lk4 + 2, lrow) = bn4.z;
        BS_(buf, lk4 + 3, lrow) = bn4.w;
        __syncthreads();
        if (kt + 1 < ND / BK) {            // prefetch next K-chunk from L2
            an  = aptr[(kt + 1) * 2];
            bn4 = bptr[(kt + 1) * 2];
        }
#pragma unroll
        for (int kk = 0; kk < BK; kk++) {
            float4 a0 = *(const float4*)&AS(buf, kk, ty * 8);
            float4 a1 = *(const float4*)&AS(buf, kk, ty * 8 + 4);
            ulonglong2 bq0 = *(const ulonglong2*)&BS_(buf, kk, tx * 8);
            ulonglong2 bq1 = *(const ulonglong2*)&BS_(buf, kk, tx * 8 + 4);
            float a[8] = {a0.x, a0.y, a0.z, a0.w, a1.x, a1.y, a1.z, a1.w};
            unsigned long long bb[4] = {bq0.x, bq0.y, bq1.x, bq1.y};
#pragma unroll
            for (int i = 0; i < 8; i++) {
                unsigned long long av;
                asm("mov.b64 %0, {%1, %1};" : "=l"(av) : "f"(a[i]));
#pragma unroll
                for (int j = 0; j < 4; j++) {
                    asm("fma.rn.f32x2 %0, %1, %2, %0;"
                        : "+l"(acc2[i][j]) : "l"(av), "l"(bb[j]));
                }
            }
        }
        buf ^= 1;
    }

    // -------- epilogue: exp, diagonal mask, positive mask, partial sums
    float rS[8], rN[8], cS[8], cN[8];
#pragma unroll
    for (int i = 0; i < 8; i++) { rS[i] = 0.f; rN[i] = 0.f; cS[i] = 0.f; cN[i] = 0.f; }
    int rk[8], ck[8];
#pragma unroll
    for (int i = 0; i < 8; i++) rk[i] = rkey[ty * 8 + i];
#pragma unroll
    for (int j = 0; j < 8; j++) ck[j] = ckey[tx * 8 + j];

#pragma unroll
    for (int i = 0; i < 8; i++) {
#pragma unroll
        for (int j4 = 0; j4 < 4; j4++) {
            union { unsigned long long u; float2 f; } cvt;
            cvt.u = acc2[i][j4];
            const int j0 = 2 * j4, j1 = j0 + 1;
            float e0 = exp2f(cvt.f.x * SCALEF);
            float e1 = exp2f(cvt.f.y * SCALEF);
            if (diag) {                       // exp(-9e15) on the diagonal -> 0
                if (ty * 8 + i == tx * 8 + j0) e0 = 0.f;
                if (ty * 8 + i == tx * 8 + j1) e1 = 0.f;
            }
            rS[i] += e0 + e1;
            cS[j0] += e0; cS[j1] += e1;
            bool m0 = (rk[i] == ck[j0]) && (rk[i] >= 0);
            bool m1 = (rk[i] == ck[j1]) && (rk[i] >= 0);
            if (m0) { rN[i] += e0; cN[j0] += e0; }
            if (m1) { rN[i] += e1; cN[j1] += e1; }
        }
    }

    // -------- block reduction (reuse tile smem; 17-stride kills bank conflicts)
#define RED(r,c) smem[(r)*17 + (c)]
    __syncthreads();
#pragma unroll
    for (int i = 0; i < 8; i++) RED(ty * 8 + i, tx) = rS[i];
    __syncthreads();
    if (tid < BM) {
        float s = 0.f;
#pragma unroll
        for (int c = 0; c < 16; c++) s += RED(tid, c);
        atomicAdd(&g_sum[row0 + tid], s);
    }
    __syncthreads();
#pragma unroll
    for (int i = 0; i < 8; i++) RED(ty * 8 + i, tx) = rN[i];
    __syncthreads();
    if (tid < BM) {
        float s = 0.f;
#pragma unroll
        for (int c = 0; c < 16; c++) s += RED(tid, c);
        atomicAdd(&g_num[row0 + tid], s);
    }
    if (!diag) {   // transposed contribution feeds the column block's rows
        __syncthreads();
#pragma unroll
        for (int j = 0; j < 8; j++) RED(tx * 8 + j, ty) = cS[j];
        __syncthreads();
        if (tid < BM) {
            float s = 0.f;
#pragma unroll
            for (int c = 0; c < 16; c++) s += RED(tid, c);
            atomicAdd(&g_sum[col0 + tid], s);
        }
        __syncthreads();
#pragma unroll
        for (int j = 0; j < 8; j++) RED(tx * 8 + j, ty) = cN[j];
        __syncthreads();
        if (tid < BM) {
            float s = 0.f;
#pragma unroll
            for (int c = 0; c < 16; c++) s += RED(tid, c);
            atomicAdd(&g_num[col0 + tid], s);
        }
    }
#undef AS
#undef BS_
#undef RED
}

// ---------------------------------------------------------------- finalize
__global__ void finalize_kernel(const int* __restrict__ rel32,
                                const void* __restrict__ tru,
                                float* __restrict__ out, int out_size) {
    __shared__ int cnt[128];              // relations are in [0,128)
    __shared__ float s_loss[256];
    __shared__ int   s_cnt[256];
    const int tid = threadIdx.x;
    const int is64 = g_is64;
    const int truw = g_truw;
    const unsigned int*  tw = (const unsigned int*)tru;
    const unsigned char* tb = (const unsigned char*)tru;
    if (tid < 128) cnt[tid] = 0;
    __syncthreads();
    for (int i = tid; i < NB; i += 256) {
        bool t = truw ? (tw[i] != 0u) : (tb[i] != 0);
        if (t) {
            int rv = is64 ? rel32[2 * i] : rel32[i];
            atomicAdd(&cnt[rv & 127], 1);
        }
    }
    __syncthreads();
    float lsum = 0.f; int lcnt = 0;
    for (int i = tid; i < NB; i += 256) {
        int rv = is64 ? rel32[2 * i] : rel32[i];
        bool t = truw ? (tw[i] != 0u) : (tb[i] != 0);
        bool hp = t && (cnt[rv & 127] >= 2);   // has_pos: another true sample, same relation
        if (hp) {
            // loss_i = log(sum_exp + 1e-8) - log(numer)
            lsum += logf(g_sum[i] + 1e-8f) - logf(g_num[i]);
            lcnt++;
        }
    }
    s_loss[tid] = lsum; s_cnt[tid] = lcnt;
    __syncthreads();
    for (int o = 128; o > 0; o >>= 1) {
        if (tid < o) { s_loss[tid] += s_loss[tid + o]; s_cnt[tid] += s_cnt[tid + o]; }
        __syncthreads();
    }
    if (tid == 0) {
        float loss = (s_cnt[0] > 0) ? (s_loss[0] / (float)s_cnt[0]) : 0.f;
        out[0] = loss;
        if (out_size > 1) out[1] = (float)s_cnt[0];
        for (int k = 2; k < out_size; k++) out[k] = 0.f;
    }
}

// ---------------------------------------------------------------- launch
extern "C" void kernel_launch(void* const* d_in, const int* in_sizes, int n_in,
                              void* d_out, int out_size) {
    const float* emb   = (const float*)d_in[0];
    const int*   rel32 = (const int*)d_in[1];
    const void*  tru   = d_in[2];
    float* out = (float*)d_out;

    init_kernel<<<NB / 256, 256>>>();
    probe_kernel<<<1, 256>>>(rel32, (const unsigned int*)tru);
    tile_kernel<<<NPAIRS, 256>>>(emb, rel32, tru);
    finalize_kernel<<<1, 256>>>(rel32, tru, out, out_size);
}

// round 15
// speedup vs baseline: 2.1959x; 2.1959x over previous
#include <cuda_runtime.h>
#include <cuda_bf16.h>
#include <cstdint>
#include <math.h>

#define NB    8192
#define ND    1024
#define BM    128
#define NT    64
#define NPAIRS (NT*(NT+1)/2)          /* 2080 upper-triangle tiles */
#define SCALEF 28.85390081777927f     /* log2(e)/0.05 */
#define KC    64                      /* K-chunk (bf16 elems) */
#define NKT   (ND/KC)                 /* 16 chunks */
#define RSTRIDE 144                   /* smem row stride bytes (9 x uint4, conflict-free) */

__device__ float g_sum[NB];
__device__ float g_num[NB];
__device__ int   g_is64;
__device__ int   g_truw;
__device__ int   g_relcnt[128];
__device__ float g_lsum;
__device__ int   g_lcnt;
__device__ __nv_bfloat16 g_hi[NB * ND];   // 16MB scratch
__device__ __nv_bfloat16 g_lo[NB * ND];

// ---- smem layout ----
#define AH_OFF 0
#define AL_OFF 18432
#define BH_OFF 36864
#define BL_OFF 55296              /* 4 tiles x 128 rows x 144B = 73728 */
#define SM_RKEY 73728             /* 128 ints */
#define SM_CKEY 74240
#define SM_RED  74752             /* RS/RN/CS/CN: 4 x 256 floats = 4096B */
#define SMEM_BYTES 78848
#define E_STRIDE 129              /* E matrix aliases tile region (66048B <= 73728) */

__device__ __forceinline__ uint32_t smem_u32(const void* p) {
    uint32_t a;
    asm("{ .reg .u64 t; cvta.to.shared.u64 t, %1; cvt.u32.u64 %0, t; }" : "=r"(a) : "l"(p));
    return a;
}
__device__ __forceinline__ float fast_exp2(float x) {
    float y; asm("ex2.approx.ftz.f32 %0, %1;" : "=f"(y) : "f"(x)); return y;
}
#define LDSM_X4(r, addr) \
    asm volatile("ldmatrix.sync.aligned.m8n8.x4.shared.b16 {%0,%1,%2,%3}, [%4];" \
        : "=r"((r)[0]), "=r"((r)[1]), "=r"((r)[2]), "=r"((r)[3]) : "r"(addr))
#define LDSM_X2(r, addr) \
    asm volatile("ldmatrix.sync.aligned.m8n8.x2.shared.b16 {%0,%1}, [%2];" \
        : "=r"((r)[0]), "=r"((r)[1]) : "r"(addr))
#define MMA16816(c, a, b) \
    asm volatile("mma.sync.aligned.m16n8k16.row.col.f32.bf16.bf16.f32 " \
        "{%0,%1,%2,%3},{%4,%5,%6,%7},{%8,%9},{%0,%1,%2,%3};" \
        : "+f"((c)[0]), "+f"((c)[1]), "+f"((c)[2]), "+f"((c)[3]) \
        : "r"((a)[0]), "r"((a)[1]), "r"((a)[2]), "r"((a)[3]), "r"((b)[0]), "r"((b)[1]))

// ---------------------------------------------------------------- init/probe
__global__ void init_kernel() {
    int i = blockIdx.x * blockDim.x + threadIdx.x;
    if (i < NB) { g_sum[i] = 0.f; g_num[i] = 0.f; }
    if (blockIdx.x == 0) {
        if (threadIdx.x < 128) g_relcnt[threadIdx.x] = 0;
        if (threadIdx.x == 128) { g_lsum = 0.f; g_lcnt = 0; }
    }
}

__global__ void probe_kernel(const int* __restrict__ rel32,
                             const unsigned int* __restrict__ truw) {
    __shared__ int rel_nz, f32_seen, gt1_seen;
    if (threadIdx.x == 0) { rel_nz = 0; f32_seen = 0; gt1_seen = 0; }
    __syncthreads();
    for (int i = 1 + 2 * threadIdx.x; i < NB; i += 2 * blockDim.x)
        if (rel32[i] != 0) rel_nz = 1;
    for (int i = threadIdx.x; i < NB / 4; i += blockDim.x) {
        unsigned int w = truw[i];
        if (w == 0x3F800000u) f32_seen = 1;
        else if (w > 1u) gt1_seen = 1;
    }
    __syncthreads();
    if (threadIdx.x == 0) {
        g_is64 = rel_nz ? 0 : 1;
        g_truw = (f32_seen || !gt1_seen) ? 1 : 0;
    }
}

// ---------------------------------------------------------------- split-convert
__global__ void convert_kernel(const float* __restrict__ emb) {
    int gid = blockIdx.x * blockDim.x + threadIdx.x;
    const float4* e4 = (const float4*)emb;
    float4 v0 = e4[gid * 2], v1 = e4[gid * 2 + 1];
    float x[8] = {v0.x, v0.y, v0.z, v0.w, v1.x, v1.y, v1.z, v1.w};
    unsigned int* HO = (unsigned int*)g_hi;
    unsigned int* LO = (unsigned int*)g_lo;
#pragma unroll
    for (int p = 0; p < 4; p++) {
        __nv_bfloat16 h0 = __float2bfloat16_rn(x[2*p]);
        __nv_bfloat16 h1 = __float2bfloat16_rn(x[2*p+1]);
        __nv_bfloat16 l0 = __float2bfloat16_rn(x[2*p]   - __bfloat162float(h0));
        __nv_bfloat16 l1 = __float2bfloat16_rn(x[2*p+1] - __bfloat162float(h1));
        unsigned short hs0 = *(unsigned short*)&h0, hs1 = *(unsigned short*)&h1;
        unsigned short ls0 = *(unsigned short*)&l0, ls1 = *(unsigned short*)&l1;
        HO[gid * 4 + p] = (unsigned int)hs0 | ((unsigned int)hs1 << 16);
        LO[gid * 4 + p] = (unsigned int)ls0 | ((unsigned int)ls1 << 16);
    }
}

// ---------------------------------------------------------------- tile kernel
// 128x128 tile per block; bf16-split 3-MMA via mma.sync (HMMA — tcgen05 is
// unavailable: harness ptxas targets plain sm_103, no 'a' features).
__global__ __launch_bounds__(256)
void tile_kernel(const int* __restrict__ rel32, const void* __restrict__ tru) {
    extern __shared__ char smem[];
    const uint32_t sb = smem_u32(smem);
    const int tid = threadIdx.x, wid = tid >> 5, lane = tid & 31;
    const int warp_m = wid & 1, warp_n = wid >> 1;    // 2x4 warp grid: 64x32 each

    int rem = blockIdx.x, bm = 0;
    while (rem >= NT - bm) { rem -= NT - bm; bm++; }
    const int bn = bm + rem;
    const int row0 = bm * BM, col0 = bn * BM;
    const bool diag = (bm == bn);

    int* rkey = (int*)(smem + SM_RKEY);
    int* ckey = (int*)(smem + SM_CKEY);
    {
        const int is64 = g_is64, truw = g_truw;
        const unsigned int*  tw = (const unsigned int*)tru;
        const unsigned char* tb = (const unsigned char*)tru;
        if (tid < BM) {
            int r = row0 + tid;
            int rv = is64 ? rel32[2 * r] : rel32[r];
            bool t = truw ? (tw[r] != 0u) : (tb[r] != 0);
            rkey[tid] = t ? rv : -1;
        } else {
            int c = col0 + (tid - BM);
            int cv = is64 ? rel32[2 * c] : rel32[c];
            bool t = truw ? (tw[c] != 0u) : (tb[c] != 0);
            ckey[tid - BM] = t ? cv : -1;
        }
    }

    float acc[4][4][4];
#pragma unroll
    for (int i = 0; i < 4; i++)
#pragma unroll
        for (int j = 0; j < 4; j++)
#pragma unroll
            for (int k = 0; k < 4; k++) acc[i][j][k] = 0.f;

    const uint4* HI = (const uint4*)g_hi;
    const uint4* LO = (const uint4*)g_lo;
    const int lrow = tid >> 1, half = tid & 1;
    const int aBase = (row0 + lrow) * 128;            // uint4 units (128/row)
    const int bBase = (col0 + lrow) * 128;
    const uint32_t sOff = lrow * RSTRIDE + half * 64;

    // ldmatrix lane addressing (precomputed per-warp constants)
    const uint32_t aRowSel = (uint32_t)(warp_m * 64 + (lane & 15)) * RSTRIDE + ((lane >> 4) << 4);
    const uint32_t bRowSel = (uint32_t)(warp_n * 32 + (lane & 7))  * RSTRIDE + (((lane >> 3) & 1) << 4);

#pragma unroll 1
    for (int kt = 0; kt < NKT; kt++) {
        __syncthreads();                               // prev chunk fully consumed
        int go = kt * 8 + half * 4;
        uint4 va[4], val[4], vb[4], vbl[4];
#pragma unroll
        for (int i = 0; i < 4; i++) {
            va[i]  = HI[aBase + go + i];  val[i] = LO[aBase + go + i];
            vb[i]  = HI[bBase + go + i];  vbl[i] = LO[bBase + go + i];
        }
#pragma unroll
        for (int i = 0; i < 4; i++) {
            *(uint4*)(smem + AH_OFF + sOff + i * 16) = va[i];
            *(uint4*)(smem + AL_OFF + sOff + i * 16) = val[i];
            *(uint4*)(smem + BH_OFF + sOff + i * 16) = vb[i];
            *(uint4*)(smem + BL_OFF + sOff + i * 16) = vbl[i];
        }
        __syncthreads();
#pragma unroll
        for (int ks = 0; ks < 4; ks++) {
            const uint32_t kb = ks * 32;               // 16 bf16 = 32 bytes
            uint32_t af[4][4], bh[4][2], bl[4][2];
#pragma unroll
            for (int mf = 0; mf < 4; mf++)
                LDSM_X4(af[mf], sb + AH_OFF + aRowSel + mf * (16 * RSTRIDE) + kb);
#pragma unroll
            for (int nf = 0; nf < 4; nf++) {
                LDSM_X2(bh[nf], sb + BH_OFF + bRowSel + nf * (8 * RSTRIDE) + kb);
                LDSM_X2(bl[nf], sb + BL_OFF + bRowSel + nf * (8 * RSTRIDE) + kb);
            }
#pragma unroll
            for (int mf = 0; mf < 4; mf++)
#pragma unroll
                for (int nf = 0; nf < 4; nf++) {
                    MMA16816(acc[mf][nf], af[mf], bh[nf]);   // hi*hi
                    MMA16816(acc[mf][nf], af[mf], bl[nf]);   // hi*lo
                }
#pragma unroll
            for (int mf = 0; mf < 4; mf++)
                LDSM_X4(af[mf], sb + AL_OFF + aRowSel + mf * (16 * RSTRIDE) + kb);  // reuse regs
#pragma unroll
            for (int mf = 0; mf < 4; mf++)
#pragma unroll
                for (int nf = 0; nf < 4; nf++)
                    MMA16816(acc[mf][nf], af[mf], bh[nf]);   // lo*hi
        }
    }
    __syncthreads();                                   // tiles dead; reuse as E

    // ---- epilogue: exp -> E[128][129] in smem ----
    float* E = (float*)smem;
    const int crow = (lane >> 2), ccol = (lane & 3) * 2;
#pragma unroll
    for (int mf = 0; mf < 4; mf++) {
#pragma unroll
        for (int nf = 0; nf < 4; nf++) {
            int r = warp_m * 64 + mf * 16 + crow;
            int c = warp_n * 32 + nf * 8 + ccol;
            float e0 = fast_exp2(acc[mf][nf][0] * SCALEF);
            float e1 = fast_exp2(acc[mf][nf][1] * SCALEF);
            float e2 = fast_exp2(acc[mf][nf][2] * SCALEF);
            float e3 = fast_exp2(acc[mf][nf][3] * SCALEF);
            if (diag) {
                if (row0 + r == col0 + c)         e0 = 0.f;
                if (row0 + r == col0 + c + 1)     e1 = 0.f;
                if (row0 + r + 8 == col0 + c)     e2 = 0.f;
                if (row0 + r + 8 == col0 + c + 1) e3 = 0.f;
            }
            E[r * E_STRIDE + c]           = e0;
            E[r * E_STRIDE + c + 1]       = e1;
            E[(r + 8) * E_STRIDE + c]     = e2;
            E[(r + 8) * E_STRIDE + c + 1] = e3;
        }
    }
    __syncthreads();

    float* RS = (float*)(smem + SM_RED);
    float* RN = RS + 256; float* CS = RS + 512; float* CN = RS + 768;
    {   // row sums
        int r = tid >> 1, ch = tid & 1, cb = ch * 64;
        int rk = rkey[r];
        float rs = 0.f, rn = 0.f;
#pragma unroll 8
        for (int c = 0; c < 64; c++) {
            float v = E[r * E_STRIDE + cb + c];
            rs += v;
            if (rk >= 0 && ckey[cb + c] == rk) rn += v;
        }
        RS[r * 2 + ch] = rs; RN[r * 2 + ch] = rn;
    }
    {   // col sums
        int c = tid >> 1, rh = tid & 1, rb = rh * 64;
        int ck = ckey[c];
        float cs = 0.f, cn = 0.f;
#pragma unroll 8
        for (int r = 0; r < 64; r++) {
            float v = E[(rb + r) * E_STRIDE + c];
            cs += v;
            if (ck >= 0 && rkey[rb + r] == ck) cn += v;
        }
        CS[c * 2 + rh] = cs; CN[c * 2 + rh] = cn;
    }
    __syncthreads();
    if (tid < BM) {
        atomicAdd(&g_sum[row0 + tid], RS[tid * 2] + RS[tid * 2 + 1]);
        atomicAdd(&g_num[row0 + tid], RN[tid * 2] + RN[tid * 2 + 1]);
    } else if (!diag) {
        int c = tid - BM;
        atomicAdd(&g_sum[col0 + c], CS[c * 2] + CS[c * 2 + 1]);
        atomicAdd(&g_num[col0 + c], CN[c * 2] + CN[c * 2 + 1]);
    }
}

// ---------------------------------------------------------------- finalize
__global__ void f1_count(const int* __restrict__ rel32, const void* __restrict__ tru) {
    __shared__ int cnt[128];
    const int tid = threadIdx.x;
    const int is64 = g_is64, truw = g_truw;
    const unsigned int*  tw = (const unsigned int*)tru;
    const unsigned char* tb = (const unsigned char*)tru;
    if (tid < 128) cnt[tid] = 0;
    __syncthreads();
    for (int i = blockIdx.x * blockDim.x + tid; i < NB; i += gridDim.x * blockDim.x) {
        bool t = truw ? (tw[i] != 0u) : (tb[i] != 0);
        if (t) {
            int rv = is64 ? rel32[2 * i] : rel32[i];
            atomicAdd(&cnt[rv & 127], 1);
        }
    }
    __syncthreads();
    if (tid < 128 && cnt[tid]) atomicAdd(&g_relcnt[tid], cnt[tid]);
}

__global__ void f2_loss(const int* __restrict__ rel32, const void* __restrict__ tru) {
    __shared__ float sl[256];
    __shared__ int   sc[256];
    const int tid = threadIdx.x;
    const int is64 = g_is64, truw = g_truw;
    const unsigned int*  tw = (const unsigned int*)tru;
    const unsigned char* tb = (const unsigned char*)tru;
    float lsum = 0.f; int lcnt = 0;
    for (int i = blockIdx.x * blockDim.x + tid; i < NB; i += gridDim.x * blockDim.x) {
        bool t = truw ? (tw[i] != 0u) : (tb[i] != 0);
        int rv = is64 ? rel32[2 * i] : rel32[i];
        if (t && g_relcnt[rv & 127] >= 2) {
            lsum += logf(g_sum[i] + 1e-8f) - logf(g_num[i]);
            lcnt++;
        }
    }
    sl[tid] = lsum; sc[tid] = lcnt;
    __syncthreads();
    for (int o = 128; o > 0; o >>= 1) {
        if (tid < o) { sl[tid] += sl[tid + o]; sc[tid] += sc[tid + o]; }
        __syncthreads();
    }
    if (tid == 0) { atomicAdd(&g_lsum, sl[0]); atomicAdd(&g_lcnt, sc[0]); }
}

__global__ void f3_out(float* __restrict__ out, int out_size) {
    if (threadIdx.x == 0) {
        int c = g_lcnt;
        out[0] = (c > 0) ? (g_lsum / (float)c) : 0.f;
        if (out_size > 1) out[1] = (float)c;
        for (int k = 2; k < out_size; k++) out[k] = 0.f;
    }
}

// ---------------------------------------------------------------- launch
extern "C" void kernel_launch(void* const* d_in, const int* in_sizes, int n_in,
                              void* d_out, int out_size) {
    const float* emb   = (const float*)d_in[0];
    const int*   rel32 = (const int*)d_in[1];
    const void*  tru   = d_in[2];
    float* out = (float*)d_out;

    cudaFuncSetAttribute(tile_kernel, cudaFuncAttributeMaxDynamicSharedMemorySize, SMEM_BYTES);

    init_kernel<<<NB / 256, 256>>>();
    probe_kernel<<<1, 256>>>(rel32, (const unsigned int*)tru);
    convert_kernel<<<NB * ND / 2048, 256>>>(emb);
    tile_kernel<<<NPAIRS, 256, SMEM_BYTES>>>(rel32, tru);
    f1_count<<<32, 256>>>(rel32, tru);
    f2_loss<<<32, 256>>>(rel32, tru);
    f3_out<<<1, 32>>>(out, out_size);
}